// round 12
// baseline (speedup 1.0000x reference)
#include <cuda_runtime.h>
#include <cuda_fp16.h>
#include <cstdint>

#define BB 8
#define TT 4096
#define DD 768
#define DI 1536
#define BT (BB*TT)            // 32768 rows
#define NT_T (TT/128)         // 32 row tiles per batch
#define NBAND 10              // score band in 128-tiles (gamma^1152 ~ 9e-6)
#define NTRI  45              // NBAND*(NBAND-1)/2
#define TILES_PER_B 275       // 45 + (32-9)*10

#define BM 128
#define BN 128
#define BKH 64                // K per stage in halves (128 bytes/row)
#define THREADS 128           // 4 warps, 64x64 warp tiles
#define TILE_BYTES 16384      // 128 rows x 128 B
#define STAGE_BYTES (2*TILE_BYTES)
#define SMEM_BYTES (3*STAGE_BYTES)   // 96 KB

// weight scratch layout (half elements); proj+gate contiguous for fused GEMM
#define W_PROJ  0
#define W_GATE  1179648
#define W_OUTP  2359296
#define W_WRITE 3538944
#define W_READ  4128768
#define W_TOTAL 4718592

// ---------------- scratch ----------------
__device__ __half g_yh[(size_t)BT*DD];       // rmsnorm output (fp16)
__device__ __half g_val[(size_t)BT*DI];      // pre-conv projection (fp16)
__device__ __half g_gate[(size_t)BT*DI];     // silu(gate projection) (fp16)
__device__ __half g_vg[(size_t)BT*DI];       // conv*gate output (fp16)
__device__ __half g_out_h[(size_t)BT*DD];    // conv-mix output (fp16: GEMM input + residual)
__device__ __half g_vt[(size_t)BB*DD*TT];    // write projection transposed [B,D,T] (fp16)
__device__ __half g_reads[(size_t)BT*DD];    // attention reads (fp16)
__device__ __half g_P[(size_t)BB*TT*TT];     // decay-weighted scores (fp16, banded tiles)
__device__ __half g_wh[W_TOTAL];             // fp16 weights

// ---------------- helpers ----------------
__device__ __forceinline__ uint32_t smem_u32(const void* p){
    uint32_t a;
    asm("{ .reg .u64 t; cvta.to.shared.u64 t, %1; cvt.u32.u64 %0, t; }" : "=r"(a) : "l"(p));
    return a;
}
__device__ __forceinline__ void cp16(uint32_t dst, const __half* src, int sz){
    asm volatile("cp.async.cg.shared.global [%0], [%1], 16, %2;" :: "r"(dst), "l"(src), "r"(sz) : "memory");
}
__device__ __forceinline__ void cpcommit(){ asm volatile("cp.async.commit_group;" ::: "memory"); }
__device__ __forceinline__ void cpwait1(){ asm volatile("cp.async.wait_group 1;" ::: "memory"); }
#define LDSM4(r0,r1,r2,r3,addr) \
    asm volatile("ldmatrix.sync.aligned.m8n8.x4.shared.b16 {%0,%1,%2,%3}, [%4];" \
      : "=r"(r0),"=r"(r1),"=r"(r2),"=r"(r3) : "r"(addr))
__device__ __forceinline__ void mma_fp16(float* c, const uint32_t* a, const uint32_t* b){
    asm volatile("mma.sync.aligned.m16n8k16.row.col.f32.f16.f16.f32 "
      "{%0,%1,%2,%3}, {%4,%5,%6,%7}, {%8,%9}, {%0,%1,%2,%3};"
      : "+f"(c[0]),"+f"(c[1]),"+f"(c[2]),"+f"(c[3])
      : "r"(a[0]),"r"(a[1]),"r"(a[2]),"r"(a[3]), "r"(b[0]),"r"(b[1]));
}

// modes
#define M_PROJGATE 0  // fused val/gate GEMM (half out, tile-routed, silu on gate half)
#define M_VT       1  // v^T = write_w @ out^T  (direct, coalesced)
#define M_SCORES   2
#define M_ATTN     3
#define M_FINAL    4
#define M_OUT      5  // fp16 store to g_out_h

__global__ void __launch_bounds__(THREADS, 2) k_mma(
    const __half* __restrict__ A, const __half* __restrict__ B, float* __restrict__ C,
    int lda, int ldb, int ldc, int K, int mode,
    const float* __restrict__ xres,
    const float* __restrict__ p_decay, const float* __restrict__ p_logalpha)
{
    extern __shared__ char smem[];
    const uint32_t sb = smem_u32(smem);
    const int t = threadIdx.x;
    const int lane = t & 31, wid = t >> 5;
    const int g = lane >> 2, tg = lane & 3;
    const int warp_m = wid & 1, warp_n = wid >> 1;   // 2 x 2 warps, WM=64, WN=64

    // ---- resolve tile ----
    const __half *Ab, *Bb;
    int bm, bn, Kloc = K, negB = 0;
    if (mode == M_SCORES){
        int b = blockIdx.y, l = blockIdx.x;
        int i, j;
        if (l < NTRI){
            i = (int)((sqrtf(8.0f*(float)l + 1.0f) - 1.0f) * 0.5f);
            while ((i+1)*(i+2)/2 <= l) i++;
            while (i*(i+1)/2 > l) i--;
            j = l - i*(i+1)/2;
        } else {
            int q = (l - NTRI) / NBAND, rmd = (l - NTRI) % NBAND;
            i = (NBAND-1) + q;
            j = i - (NBAND-1) + rmd;
        }
        bm = i*128; bn = j*128;
        const __half* Ob = g_out_h + (size_t)b*TT*DD;
        Ab = Ob + (size_t)bm*DD;
        Bb = Ob + (long long)(bn-1)*DD;   // shifted keys; row -1 when bn==0
        negB = (bn == 0);
        lda = DD; ldb = DD; Kloc = DD;
    } else if (mode == M_ATTN){
        int b = blockIdx.z, it = blockIdx.y;
        bm = it*128; bn = blockIdx.x*128;
        int j0 = it - (NBAND-1); if (j0 < 0) j0 = 0;
        const int k0start = j0*128;
        Ab = g_P + (size_t)b*TT*TT + (size_t)bm*TT + k0start;
        Bb = g_vt + (size_t)b*DD*TT + (size_t)bn*TT + k0start;
        lda = TT; ldb = TT; Kloc = (it - j0 + 1)*128;
    } else if (mode == M_VT){
        bm = blockIdx.y*128; bn = blockIdx.x*128;
        Ab = A + (size_t)bm*lda;                                // write_w rows (d)
        Bb = B + (size_t)blockIdx.z*TT*DD + (size_t)bn*ldb;     // out rows (t) of batch z
    } else {
        bm = blockIdx.y*128; bn = blockIdx.x*128;
        Ab = A + (size_t)bm*lda; Bb = B + (size_t)bn*ldb;
    }

    // ---- staging bases: 128 threads x 8 chunks; row = (t>>3)+16*i, c = t&7 ----
    const int r0 = t >> 3;             // 0..15
    const int c0 = t & 7;
    const __half* aSrc0 = Ab + (size_t)r0*lda + c0*8;
    const __half* bSrcR = Bb + (size_t)r0*ldb + c0*8;       // real B base
    const int bP0 = (negB && r0 == 0) ? 0 : 16;             // chunk-0 predicate
    const __half* bSrc0 = bP0 ? bSrcR : Ab;                 // safe addr when zfill
    const uint32_t dOff0 = (uint32_t)(r0*128 + ((c0 ^ (r0 & 7)) << 4));
    uint32_t aAddr[3], bAddr[3];
    #pragma unroll
    for (int i = 0; i < 3; i++){
        aAddr[i] = sb + (uint32_t)i * STAGE_BYTES;
        bAddr[i] = aAddr[i] + TILE_BYTES;
    }

    // ---- ldmatrix per-lane row offsets (bytes) ----
    const int lane7 = lane & 7;
    uint32_t rowA[4], rowB[4];
    #pragma unroll
    for (int mt = 0; mt < 4; mt++)
        rowA[mt] = (uint32_t)((warp_m*64 + mt*16 + (lane & 15)) * 128);
    #pragma unroll
    for (int np = 0; np < 4; np++)
        rowB[np] = (uint32_t)((warp_n*64 + np*16 + ((lane >> 4) << 3) + lane7) * 128);
    const int a_chi = lane >> 4;          // 0/1
    const int b_chi = (lane >> 3) & 1;    // 0/1

    float acc[4][8][4] = {};
    const int NS = Kloc / BKH;

    // prologue: stages 0 and 1 (always commit two groups)
    #pragma unroll
    for (int i = 0; i < 8; i++){
        cp16(aAddr[0] + dOff0 + 2048*i, aSrc0 + (size_t)(16*i)*lda, 16);
        cp16(bAddr[0] + dOff0 + 2048*i, (i ? bSrcR + (size_t)(16*i)*ldb : bSrc0), i ? 16 : bP0);
    }
    cpcommit();
    if (NS > 1){
        #pragma unroll
        for (int i = 0; i < 8; i++){
            cp16(aAddr[1] + dOff0 + 2048*i, aSrc0 + (size_t)(16*i)*lda + BKH, 16);
            cp16(bAddr[1] + dOff0 + 2048*i, (i ? bSrcR + (size_t)(16*i)*ldb : bSrc0) + BKH, i ? 16 : bP0);
        }
    }
    cpcommit();

    for (int s = 0; s < NS; s++){
        cpwait1();                 // stage s complete (leave s+1 in flight)
        __syncthreads();

        if (s + 2 < NS){
            const int nb = (s+2) % 3, k0 = (s+2)*BKH;
            #pragma unroll
            for (int i = 0; i < 8; i++){
                cp16(aAddr[nb] + dOff0 + 2048*i, aSrc0 + (size_t)(16*i)*lda + k0, 16);
                cp16(bAddr[nb] + dOff0 + 2048*i, (i ? bSrcR + (size_t)(16*i)*ldb : bSrc0) + k0, i ? 16 : bP0);
            }
        }
        cpcommit();

        const int buf = s % 3;
        const uint32_t Ab0 = aAddr[buf], Bb0 = bAddr[buf];
        #pragma unroll
        for (int ks = 0; ks < 4; ks++){
            const uint32_t csA = (uint32_t)(((2*ks + a_chi) ^ lane7) << 4);
            const uint32_t csB = (uint32_t)(((2*ks + b_chi) ^ lane7) << 4);
            uint32_t af[4][4], bf[8][2];
            #pragma unroll
            for (int mt = 0; mt < 4; mt++)
                LDSM4(af[mt][0], af[mt][1], af[mt][2], af[mt][3], Ab0 + rowA[mt] + csA);
            #pragma unroll
            for (int np = 0; np < 4; np++)
                LDSM4(bf[np*2][0], bf[np*2][1], bf[np*2+1][0], bf[np*2+1][1], Bb0 + rowB[np] + csB);
            #pragma unroll
            for (int mt = 0; mt < 4; mt++)
                #pragma unroll
                for (int nt = 0; nt < 8; nt++)
                    mma_fp16(acc[mt][nt], af[mt], bf[nt]);
        }
    }

    // ---------------- epilogues ----------------
    if (mode == M_SCORES){
        const float gammaLg = logf(1.0f / (1.0f + expf(-p_decay[0])));
        const int b = blockIdx.y;
        float rowE[8], colE[16];
        #pragma unroll
        for (int mt = 0; mt < 4; mt++)
            #pragma unroll
            for (int half = 0; half < 2; half++)
                rowE[mt*2+half] = __expf((float)(bm + warp_m*64 + mt*16 + g + half*8) * gammaLg);
        #pragma unroll
        for (int nt = 0; nt < 8; nt++)
            #pragma unroll
            for (int k = 0; k < 2; k++)
                colE[nt*2+k] = __expf(-(float)(bn + warp_n*64 + nt*8 + tg*2 + k + 1) * gammaLg);
        #pragma unroll
        for (int mt = 0; mt < 4; mt++){
            #pragma unroll
            for (int half = 0; half < 2; half++){
                const int r = warp_m*64 + mt*16 + g + half*8;
                const int trow = bm + r;
                const float er = rowE[mt*2+half];
                #pragma unroll
                for (int nt = 0; nt < 8; nt++){
                    const int c = warp_n*64 + nt*8 + tg*2;
                    const int d0 = trow - (bn + c) - 1;
                    float o0 = (d0 >= 0) ? acc[mt][nt][half*2]   * er * colE[nt*2]   : 0.f;
                    float o1 = (d0 >= 1) ? acc[mt][nt][half*2+1] * er * colE[nt*2+1] : 0.f;
                    __half* Pb = g_P + (size_t)b*TT*TT + (size_t)trow*TT + bn + c;
                    *(__half2*)Pb = __floats2half2_rn(o0, o1);
                }
            }
        }
        return;
    }

    float alpha = 0.f;
    if (mode == M_FINAL) alpha = expf(p_logalpha[0]);
    __half* pgBase = nullptr; int pgCol = 0; bool isGate = false;
    if (mode == M_PROJGATE){
        isGate = (bn >= DI);
        pgBase = isGate ? g_gate : g_val;
        pgCol = isGate ? bn - DI : bn;
    }
    __half* vtBase = (mode == M_VT) ? g_vt + (size_t)blockIdx.z*DD*TT : nullptr;
    __half* rdBase = (mode == M_ATTN) ? g_reads + (size_t)blockIdx.z*TT*DD : nullptr;

    #pragma unroll
    for (int mt = 0; mt < 4; mt++){
        #pragma unroll
        for (int half = 0; half < 2; half++){
            const int r = warp_m*64 + mt*16 + g + half*8;
            #pragma unroll
            for (int nt = 0; nt < 8; nt++){
                const int c = warp_n*64 + nt*8 + tg*2;
                float v0 = acc[mt][nt][half*2];
                float v1 = acc[mt][nt][half*2 + 1];
                if (mode == M_FINAL){
                    size_t idx = (size_t)(bm + r)*DD + bn + c;
                    float2 xv = *(const float2*)(xres + idx);
                    __half2 oh = *(const __half2*)(g_out_h + idx);
                    *(float2*)(C + idx) = make_float2(xv.x + __low2float(oh) + alpha*v0,
                                                      xv.y + __high2float(oh) + alpha*v1);
                } else if (mode == M_OUT){
                    size_t idx = (size_t)(bm + r)*DD + bn + c;
                    *(__half2*)(g_out_h + idx) = __floats2half2_rn(v0, v1);
                } else if (mode == M_VT){
                    *(__half2*)(vtBase + (size_t)(bm + r)*TT + bn + c) = __floats2half2_rn(v0, v1);
                } else if (mode == M_ATTN){
                    *(__half2*)(rdBase + (size_t)(bm + r)*DD + bn + c) = __floats2half2_rn(v0, v1);
                } else { // M_PROJGATE
                    if (isGate){
                        v0 = v0 / (1.f + __expf(-v0));
                        v1 = v1 / (1.f + __expf(-v1));
                    }
                    *(__half2*)(pgBase + (size_t)(bm + r)*DI + pgCol + c) = __floats2half2_rn(v0, v1);
                }
            }
        }
    }
}

// ---------------- weight rounding (5 matrices -> g_wh) ----------------
__global__ void k_wround(const float* __restrict__ s0, const float* __restrict__ s1,
                         const float* __restrict__ s2, const float* __restrict__ s3,
                         const float* __restrict__ s4)
{
    int m = blockIdx.y;
    int idx = blockIdx.x * 256 + threadIdx.x;
    const float* src; int off, n;
    switch (m){
        case 0: src = s0; off = W_PROJ;  n = DI*DD; break;
        case 1: src = s1; off = W_GATE;  n = DI*DD; break;
        case 2: src = s2; off = W_OUTP;  n = DD*DI; break;
        case 3: src = s3; off = W_WRITE; n = DD*DD; break;
        default: src = s4; off = W_READ; n = DD*DD; break;
    }
    if (idx < n) g_wh[off + idx] = __float2half_rn(src[idx]);
}

// ---------------- rmsnorm: 192 threads/row, float4 + warp shuffle ----------------
__global__ void __launch_bounds__(192) k_rms(const float* __restrict__ x, const float* __restrict__ w) {
    const int row = blockIdx.x;
    const int tid = threadIdx.x;           // 0..191
    const int lane = tid & 31, wd = tid >> 5;
    const float4 v = ((const float4*)(x + (size_t)row * DD))[tid];
    float s = v.x*v.x + v.y*v.y + v.z*v.z + v.w*v.w;
    #pragma unroll
    for (int off = 16; off > 0; off >>= 1)
        s += __shfl_xor_sync(0xffffffffu, s, off);
    __shared__ float ws[6];
    if (lane == 0) ws[wd] = s;
    __syncthreads();
    float tot = ws[0] + ws[1] + ws[2] + ws[3] + ws[4] + ws[5];
    float r = rsqrtf(tot * (1.0f/DD) + 1e-5f);
    const float4 wv = ((const float4*)w)[tid];
    __half2* yr = (__half2*)(g_yh + (size_t)row * DD);
    yr[tid*2]   = __floats2half2_rn(v.x * r * wv.x, v.y * r * wv.y);
    yr[tid*2+1] = __floats2half2_rn(v.z * r * wv.z, v.w * r * wv.w);
}

// ---- depthwise causal conv + (pre-silu'd) gate (half2 channels, 4 t/thread) ----
#define E2 (DI/2)
__global__ void k_conv(const float* __restrict__ cw, const float* __restrict__ cb) {
    size_t idx = (size_t)blockIdx.x * 256 + threadIdx.x;   // (BT/4)*E2 threads
    int e2 = (int)(idx % E2);
    size_t q = idx / E2;
    int tq = (int)(q % (TT/4));
    int b  = (int)(q / (TT/4));
    int t0 = tq * 4;
    const int e0 = e2 * 2;
    size_t base = (((size_t)b*TT + t0)*DI >> 1) + e2;       // half2 index
    const float4 c0 = ((const float4*)cw)[e0];
    const float4 c1 = ((const float4*)cw)[e0+1];
    const float2 bias = ((const float2*)cb)[e2];
    const __half2* valp = (const __half2*)g_val;
    const __half2* gatep = (const __half2*)g_gate;          // already silu'd
    __half2* vgp = (__half2*)g_vg;
    float vl[7], vh[7];
    #pragma unroll
    for (int i = 0; i < 7; i++){
        int tt = t0 - 3 + i;
        if (tt >= 0){
            __half2 hv = valp[base + (size_t)(i-3)*E2];
            vl[i] = __low2float(hv); vh[i] = __high2float(hv);
        } else { vl[i] = 0.f; vh[i] = 0.f; }
    }
    #pragma unroll
    for (int j = 0; j < 4; j++){
        float s0 = bias.x + c0.x*vl[j] + c0.y*vl[j+1] + c0.z*vl[j+2] + c0.w*vl[j+3];
        float s1 = bias.y + c1.x*vh[j] + c1.y*vh[j+1] + c1.z*vh[j+2] + c1.w*vh[j+3];
        float sv0 = s0 / (1.f + __expf(-s0));
        float sv1 = s1 / (1.f + __expf(-s1));
        __half2 gh = gatep[base + (size_t)j*E2];
        vgp[base + (size_t)j*E2] = __floats2half2_rn(sv0 * __low2float(gh), sv1 * __high2float(gh));
    }
}

// ---------------- launch ----------------
extern "C" void kernel_launch(void* const* d_in, const int* in_sizes, int n_in,
                              void* d_out, int out_size) {
    const float* x         = (const float*)d_in[0];
    const float* norm_w    = (const float*)d_in[1];
    const float* proj_w    = (const float*)d_in[2];
    const float* gate_w    = (const float*)d_in[3];
    const float* conv_w    = (const float*)d_in[4];
    const float* conv_b    = (const float*)d_in[5];
    const float* out_projw = (const float*)d_in[6];
    const float* write_w   = (const float*)d_in[7];
    const float* read_w    = (const float*)d_in[8];
    const float* decay     = (const float*)d_in[9];
    const float* log_alpha = (const float*)d_in[10];
    float* out = (float*)d_out;

    cudaFuncSetAttribute(k_mma, cudaFuncAttributeMaxDynamicSharedMemorySize, SMEM_BYTES);

    __half *p_yh, *p_vg, *p_outh, *p_reads, *p_wh;
    cudaGetSymbolAddress((void**)&p_yh,    g_yh);
    cudaGetSymbolAddress((void**)&p_vg,    g_vg);
    cudaGetSymbolAddress((void**)&p_outh,  g_out_h);
    cudaGetSymbolAddress((void**)&p_reads, g_reads);
    cudaGetSymbolAddress((void**)&p_wh,    g_wh);

    // 0) round weights to fp16
    k_wround<<<dim3((DI*DD + 255)/256, 5), 256>>>(proj_w, gate_w, out_projw, write_w, read_w);
    // 1) rmsnorm (fp16 out)
    k_rms<<<BT, 192>>>(x, norm_w);
    // 2) fused: [val | silu(gate)] = y @ [proj_w ; gate_w]^T  (fp16 out, N=3072)
    k_mma<<<dim3(2*DI/128, BT/128), THREADS, SMEM_BYTES>>>(p_yh, p_wh + W_PROJ, nullptr, DD, DD, DI, DD, M_PROJGATE, nullptr, nullptr, nullptr);
    // 3) vg = silu(conv(val)+b) * gate_silu  (fp16 out)
    k_conv<<<(unsigned)((size_t)BT/4*E2/256), 256>>>(conv_w, conv_b);
    // 4) out = vg @ out_proj_w^T  (fp16)
    k_mma<<<dim3(DD/128, BT/128), THREADS, SMEM_BYTES>>>(p_vg, p_wh + W_OUTP, nullptr, DI, DI, DD, DI, M_OUT, nullptr, nullptr, nullptr);
    // 5) v^T = write_w @ out^T -> g_vt (direct, coalesced)
    k_mma<<<dim3(TT/128, DD/128, BB), THREADS, SMEM_BYTES>>>(p_wh + W_WRITE, p_outh, nullptr, DD, DD, 0, DD, M_VT, nullptr, nullptr, nullptr);
    // 6) P = decay-masked (out @ shifted-out^T), banded lower tiles (factorized exp)
    k_mma<<<dim3(TILES_PER_B, BB), THREADS, SMEM_BYTES>>>(nullptr, nullptr, nullptr, 0, 0, 0, DD, M_SCORES, nullptr, decay, nullptr);
    // 7) reads = P @ v  (banded K)
    k_mma<<<dim3(DD/128, NT_T, BB), THREADS, SMEM_BYTES>>>(nullptr, nullptr, nullptr, 0, 0, 0, 0, M_ATTN, nullptr, nullptr, nullptr);
    // 8) final = x + out + exp(log_alpha) * (reads @ read_w^T)
    k_mma<<<dim3(DD/128, BT/128), THREADS, SMEM_BYTES>>>(p_reads, p_wh + W_READ, out, DD, DD, DD, DD, M_FINAL, x, nullptr, log_alpha);
}

// round 13
// speedup vs baseline: 1.0248x; 1.0248x over previous
#include <cuda_runtime.h>
#include <cuda_fp16.h>
#include <cstdint>

#define BB 8
#define TT 4096
#define DD 768
#define DI 1536
#define BT (BB*TT)            // 32768 rows
#define NT_T (TT/128)         // 32 row tiles per batch
#define NBAND 10              // score band in 128-tiles (gamma^1152 ~ 9e-6)
#define NTRI  45              // NBAND*(NBAND-1)/2
#define TILES_PER_B 275       // 45 + (32-9)*10

#define BM 128
#define BN 128
#define BKH 64                // K per stage in halves (128 bytes/row)
#define THREADS 128           // 4 warps, 64x64 warp tiles
#define TILE_BYTES 16384      // 128 rows x 128 B
#define STAGE_BYTES (2*TILE_BYTES)
#define SMEM_BYTES (2*STAGE_BYTES)   // 64 KB -> 3 CTAs/SM

// weight scratch layout (half elements); proj+gate contiguous for fused GEMM
#define W_PROJ  0
#define W_GATE  1179648
#define W_OUTP  2359296
#define W_WRITE 3538944
#define W_READ  4128768
#define W_TOTAL 4718592

// ---------------- scratch ----------------
__device__ __half g_yh[(size_t)BT*DD];       // rmsnorm output (fp16)
__device__ __half g_val[(size_t)BT*DI];      // pre-conv projection (fp16)
__device__ __half g_gate[(size_t)BT*DI];     // silu(gate projection) (fp16)
__device__ __half g_vg[(size_t)BT*DI];       // conv*gate output (fp16)
__device__ __half g_out_h[(size_t)BT*DD];    // conv-mix output (fp16: GEMM input + residual)
__device__ __half g_vt[(size_t)BB*DD*TT];    // write projection transposed [B,D,T] (fp16)
__device__ __half g_reads[(size_t)BT*DD];    // attention reads (fp16)
__device__ __half g_P[(size_t)BB*TT*TT];     // decay-weighted scores (fp16, banded tiles)
__device__ __half g_wh[W_TOTAL];             // fp16 weights

// ---------------- helpers ----------------
__device__ __forceinline__ uint32_t smem_u32(const void* p){
    uint32_t a;
    asm("{ .reg .u64 t; cvta.to.shared.u64 t, %1; cvt.u32.u64 %0, t; }" : "=r"(a) : "l"(p));
    return a;
}
__device__ __forceinline__ void cp16(uint32_t dst, const __half* src, int sz){
    asm volatile("cp.async.cg.shared.global [%0], [%1], 16, %2;" :: "r"(dst), "l"(src), "r"(sz) : "memory");
}
__device__ __forceinline__ void cpcommit(){ asm volatile("cp.async.commit_group;" ::: "memory"); }
__device__ __forceinline__ void cpwait0(){ asm volatile("cp.async.wait_group 0;" ::: "memory"); }
#define LDSM4(r0,r1,r2,r3,addr) \
    asm volatile("ldmatrix.sync.aligned.m8n8.x4.shared.b16 {%0,%1,%2,%3}, [%4];" \
      : "=r"(r0),"=r"(r1),"=r"(r2),"=r"(r3) : "r"(addr))
__device__ __forceinline__ void mma_fp16(float* c, const uint32_t* a, const uint32_t* b){
    asm volatile("mma.sync.aligned.m16n8k16.row.col.f32.f16.f16.f32 "
      "{%0,%1,%2,%3}, {%4,%5,%6,%7}, {%8,%9}, {%0,%1,%2,%3};"
      : "+f"(c[0]),"+f"(c[1]),"+f"(c[2]),"+f"(c[3])
      : "r"(a[0]),"r"(a[1]),"r"(a[2]),"r"(a[3]), "r"(b[0]),"r"(b[1]));
}

// modes
#define M_PROJGATE 0  // fused val/gate GEMM (half out, tile-routed, silu on gate half)
#define M_VT       1  // v^T = write_w @ out^T  (direct, coalesced)
#define M_SCORES   2
#define M_ATTN     3
#define M_FINAL    4
#define M_OUT      5  // fp16 store to g_out_h

__global__ void __launch_bounds__(THREADS, 3) k_mma(
    const __half* __restrict__ A, const __half* __restrict__ B, float* __restrict__ C,
    int lda, int ldb, int ldc, int K, int mode,
    const float* __restrict__ xres,
    const float* __restrict__ p_decay, const float* __restrict__ p_logalpha)
{
    extern __shared__ char smem[];
    const uint32_t sb = smem_u32(smem);
    const int t = threadIdx.x;
    const int lane = t & 31, wid = t >> 5;
    const int g = lane >> 2, tg = lane & 3;
    const int warp_m = wid & 1, warp_n = wid >> 1;   // 2 x 2 warps, WM=64, WN=64

    // ---- resolve tile ----
    const __half *Ab, *Bb;
    int bm, bn, Kloc = K, negB = 0;
    if (mode == M_SCORES){
        int b = blockIdx.y, l = blockIdx.x;
        int i, j;
        if (l < NTRI){
            i = (int)((sqrtf(8.0f*(float)l + 1.0f) - 1.0f) * 0.5f);
            while ((i+1)*(i+2)/2 <= l) i++;
            while (i*(i+1)/2 > l) i--;
            j = l - i*(i+1)/2;
        } else {
            int q = (l - NTRI) / NBAND, rmd = (l - NTRI) % NBAND;
            i = (NBAND-1) + q;
            j = i - (NBAND-1) + rmd;
        }
        bm = i*128; bn = j*128;
        const __half* Ob = g_out_h + (size_t)b*TT*DD;
        Ab = Ob + (size_t)bm*DD;
        Bb = Ob + (long long)(bn-1)*DD;   // shifted keys; row -1 when bn==0
        negB = (bn == 0);
        lda = DD; ldb = DD; Kloc = DD;
    } else if (mode == M_ATTN){
        int b = blockIdx.z, it = blockIdx.y;
        bm = it*128; bn = blockIdx.x*128;
        int j0 = it - (NBAND-1); if (j0 < 0) j0 = 0;
        const int k0start = j0*128;
        Ab = g_P + (size_t)b*TT*TT + (size_t)bm*TT + k0start;
        Bb = g_vt + (size_t)b*DD*TT + (size_t)bn*TT + k0start;
        lda = TT; ldb = TT; Kloc = (it - j0 + 1)*128;
    } else if (mode == M_VT){
        bm = blockIdx.y*128; bn = blockIdx.x*128;
        Ab = A + (size_t)bm*lda;                                // write_w rows (d)
        Bb = B + (size_t)blockIdx.z*TT*DD + (size_t)bn*ldb;     // out rows (t) of batch z
    } else {
        bm = blockIdx.y*128; bn = blockIdx.x*128;
        Ab = A + (size_t)bm*lda; Bb = B + (size_t)bn*ldb;
    }

    // ---- staging bases: 128 threads x 8 chunks; row = (t>>3)+16*i, c = t&7 ----
    const int r0 = t >> 3;             // 0..15
    const int c0 = t & 7;
    const __half* aSrc0 = Ab + (size_t)r0*lda + c0*8;
    const __half* bSrcR = Bb + (size_t)r0*ldb + c0*8;       // real B base
    const int bP0 = (negB && r0 == 0) ? 0 : 16;             // chunk-0 predicate
    const __half* bSrc0 = bP0 ? bSrcR : Ab;                 // safe addr when zfill
    const uint32_t dOff0 = (uint32_t)(r0*128 + ((c0 ^ (r0 & 7)) << 4));
    uint32_t aAddr[2], bAddr[2];
    #pragma unroll
    for (int i = 0; i < 2; i++){
        aAddr[i] = sb + (uint32_t)i * STAGE_BYTES;
        bAddr[i] = aAddr[i] + TILE_BYTES;
    }

    // ---- ldmatrix per-lane row offsets (bytes) ----
    const int lane7 = lane & 7;
    uint32_t rowA[4], rowB[4];
    #pragma unroll
    for (int mt = 0; mt < 4; mt++)
        rowA[mt] = (uint32_t)((warp_m*64 + mt*16 + (lane & 15)) * 128);
    #pragma unroll
    for (int np = 0; np < 4; np++)
        rowB[np] = (uint32_t)((warp_n*64 + np*16 + ((lane >> 4) << 3) + lane7) * 128);
    const int a_chi = lane >> 4;          // 0/1
    const int b_chi = (lane >> 3) & 1;    // 0/1

    float acc[4][8][4] = {};
    const int NS = Kloc / BKH;

    // prologue: stage 0
    #pragma unroll
    for (int i = 0; i < 8; i++){
        cp16(aAddr[0] + dOff0 + 2048*i, aSrc0 + (size_t)(16*i)*lda, 16);
        cp16(bAddr[0] + dOff0 + 2048*i, (i ? bSrcR + (size_t)(16*i)*ldb : bSrc0), i ? 16 : bP0);
    }
    cpcommit();

    for (int s = 0; s < NS; s++){
        cpwait0();                 // stage s resident
        __syncthreads();           // visibility + all warps done with the other buffer

        if (s + 1 < NS){           // issue stage s+1 into the other buffer
            const int nb = (s+1) & 1, k0 = (s+1)*BKH;
            #pragma unroll
            for (int i = 0; i < 8; i++){
                cp16(aAddr[nb] + dOff0 + 2048*i, aSrc0 + (size_t)(16*i)*lda + k0, 16);
                cp16(bAddr[nb] + dOff0 + 2048*i, (i ? bSrcR + (size_t)(16*i)*ldb : bSrc0) + k0, i ? 16 : bP0);
            }
        }
        cpcommit();

        const int buf = s & 1;
        const uint32_t Ab0 = aAddr[buf], Bb0 = bAddr[buf];
        #pragma unroll
        for (int ks = 0; ks < 4; ks++){
            const uint32_t csA = (uint32_t)(((2*ks + a_chi) ^ lane7) << 4);
            const uint32_t csB = (uint32_t)(((2*ks + b_chi) ^ lane7) << 4);
            uint32_t af[4][4], bf[8][2];
            #pragma unroll
            for (int mt = 0; mt < 4; mt++)
                LDSM4(af[mt][0], af[mt][1], af[mt][2], af[mt][3], Ab0 + rowA[mt] + csA);
            #pragma unroll
            for (int np = 0; np < 4; np++)
                LDSM4(bf[np*2][0], bf[np*2][1], bf[np*2+1][0], bf[np*2+1][1], Bb0 + rowB[np] + csB);
            #pragma unroll
            for (int mt = 0; mt < 4; mt++)
                #pragma unroll
                for (int nt = 0; nt < 8; nt++)
                    mma_fp16(acc[mt][nt], af[mt], bf[nt]);
        }
    }

    // ---------------- epilogues ----------------
    if (mode == M_SCORES){
        const float gammaLg = logf(1.0f / (1.0f + expf(-p_decay[0])));
        const int b = blockIdx.y;
        float rowE[8], colE[16];
        #pragma unroll
        for (int mt = 0; mt < 4; mt++)
            #pragma unroll
            for (int half = 0; half < 2; half++)
                rowE[mt*2+half] = __expf((float)(bm + warp_m*64 + mt*16 + g + half*8) * gammaLg);
        #pragma unroll
        for (int nt = 0; nt < 8; nt++)
            #pragma unroll
            for (int k = 0; k < 2; k++)
                colE[nt*2+k] = __expf(-(float)(bn + warp_n*64 + nt*8 + tg*2 + k + 1) * gammaLg);
        #pragma unroll
        for (int mt = 0; mt < 4; mt++){
            #pragma unroll
            for (int half = 0; half < 2; half++){
                const int r = warp_m*64 + mt*16 + g + half*8;
                const int trow = bm + r;
                const float er = rowE[mt*2+half];
                #pragma unroll
                for (int nt = 0; nt < 8; nt++){
                    const int c = warp_n*64 + nt*8 + tg*2;
                    const int d0 = trow - (bn + c) - 1;
                    float o0 = (d0 >= 0) ? acc[mt][nt][half*2]   * er * colE[nt*2]   : 0.f;
                    float o1 = (d0 >= 1) ? acc[mt][nt][half*2+1] * er * colE[nt*2+1] : 0.f;
                    __half* Pb = g_P + (size_t)b*TT*TT + (size_t)trow*TT + bn + c;
                    *(__half2*)Pb = __floats2half2_rn(o0, o1);
                }
            }
        }
        return;
    }

    float alpha = 0.f;
    if (mode == M_FINAL) alpha = expf(p_logalpha[0]);
    __half* pgBase = nullptr; int pgCol = 0; bool isGate = false;
    if (mode == M_PROJGATE){
        isGate = (bn >= DI);
        pgBase = isGate ? g_gate : g_val;
        pgCol = isGate ? bn - DI : bn;
    }
    __half* vtBase = (mode == M_VT) ? g_vt + (size_t)blockIdx.z*DD*TT : nullptr;
    __half* rdBase = (mode == M_ATTN) ? g_reads + (size_t)blockIdx.z*TT*DD : nullptr;

    #pragma unroll
    for (int mt = 0; mt < 4; mt++){
        #pragma unroll
        for (int half = 0; half < 2; half++){
            const int r = warp_m*64 + mt*16 + g + half*8;
            #pragma unroll
            for (int nt = 0; nt < 8; nt++){
                const int c = warp_n*64 + nt*8 + tg*2;
                float v0 = acc[mt][nt][half*2];
                float v1 = acc[mt][nt][half*2 + 1];
                if (mode == M_FINAL){
                    size_t idx = (size_t)(bm + r)*DD + bn + c;
                    float2 xv = *(const float2*)(xres + idx);
                    __half2 oh = *(const __half2*)(g_out_h + idx);
                    *(float2*)(C + idx) = make_float2(xv.x + __low2float(oh) + alpha*v0,
                                                      xv.y + __high2float(oh) + alpha*v1);
                } else if (mode == M_OUT){
                    size_t idx = (size_t)(bm + r)*DD + bn + c;
                    *(__half2*)(g_out_h + idx) = __floats2half2_rn(v0, v1);
                } else if (mode == M_VT){
                    *(__half2*)(vtBase + (size_t)(bm + r)*TT + bn + c) = __floats2half2_rn(v0, v1);
                } else if (mode == M_ATTN){
                    *(__half2*)(rdBase + (size_t)(bm + r)*DD + bn + c) = __floats2half2_rn(v0, v1);
                } else { // M_PROJGATE
                    if (isGate){
                        v0 = v0 / (1.f + __expf(-v0));
                        v1 = v1 / (1.f + __expf(-v1));
                    }
                    *(__half2*)(pgBase + (size_t)(bm + r)*DI + pgCol + c) = __floats2half2_rn(v0, v1);
                }
            }
        }
    }
}

// ---------------- weight rounding (5 matrices -> g_wh) ----------------
__global__ void k_wround(const float* __restrict__ s0, const float* __restrict__ s1,
                         const float* __restrict__ s2, const float* __restrict__ s3,
                         const float* __restrict__ s4)
{
    int m = blockIdx.y;
    int idx = blockIdx.x * 256 + threadIdx.x;
    const float* src; int off, n;
    switch (m){
        case 0: src = s0; off = W_PROJ;  n = DI*DD; break;
        case 1: src = s1; off = W_GATE;  n = DI*DD; break;
        case 2: src = s2; off = W_OUTP;  n = DD*DI; break;
        case 3: src = s3; off = W_WRITE; n = DD*DD; break;
        default: src = s4; off = W_READ; n = DD*DD; break;
    }
    if (idx < n) g_wh[off + idx] = __float2half_rn(src[idx]);
}

// ---------------- rmsnorm: 192 threads/row, float4 + warp shuffle ----------------
__global__ void __launch_bounds__(192) k_rms(const float* __restrict__ x, const float* __restrict__ w) {
    const int row = blockIdx.x;
    const int tid = threadIdx.x;           // 0..191
    const int lane = tid & 31, wd = tid >> 5;
    const float4 v = ((const float4*)(x + (size_t)row * DD))[tid];
    float s = v.x*v.x + v.y*v.y + v.z*v.z + v.w*v.w;
    #pragma unroll
    for (int off = 16; off > 0; off >>= 1)
        s += __shfl_xor_sync(0xffffffffu, s, off);
    __shared__ float ws[6];
    if (lane == 0) ws[wd] = s;
    __syncthreads();
    float tot = ws[0] + ws[1] + ws[2] + ws[3] + ws[4] + ws[5];
    float r = rsqrtf(tot * (1.0f/DD) + 1e-5f);
    const float4 wv = ((const float4*)w)[tid];
    __half2* yr = (__half2*)(g_yh + (size_t)row * DD);
    yr[tid*2]   = __floats2half2_rn(v.x * r * wv.x, v.y * r * wv.y);
    yr[tid*2+1] = __floats2half2_rn(v.z * r * wv.z, v.w * r * wv.w);
}

// ---- depthwise causal conv + (pre-silu'd) gate (half2 channels, 4 t/thread) ----
#define E2 (DI/2)
__global__ void k_conv(const float* __restrict__ cw, const float* __restrict__ cb) {
    size_t idx = (size_t)blockIdx.x * 256 + threadIdx.x;   // (BT/4)*E2 threads
    int e2 = (int)(idx % E2);
    size_t q = idx / E2;
    int tq = (int)(q % (TT/4));
    int b  = (int)(q / (TT/4));
    int t0 = tq * 4;
    const int e0 = e2 * 2;
    size_t base = (((size_t)b*TT + t0)*DI >> 1) + e2;       // half2 index
    const float4 c0 = ((const float4*)cw)[e0];
    const float4 c1 = ((const float4*)cw)[e0+1];
    const float2 bias = ((const float2*)cb)[e2];
    const __half2* valp = (const __half2*)g_val;
    const __half2* gatep = (const __half2*)g_gate;          // already silu'd
    __half2* vgp = (__half2*)g_vg;
    float vl[7], vh[7];
    #pragma unroll
    for (int i = 0; i < 7; i++){
        int tt = t0 - 3 + i;
        if (tt >= 0){
            __half2 hv = valp[base + (size_t)(i-3)*E2];
            vl[i] = __low2float(hv); vh[i] = __high2float(hv);
        } else { vl[i] = 0.f; vh[i] = 0.f; }
    }
    #pragma unroll
    for (int j = 0; j < 4; j++){
        float s0 = bias.x + c0.x*vl[j] + c0.y*vl[j+1] + c0.z*vl[j+2] + c0.w*vl[j+3];
        float s1 = bias.y + c1.x*vh[j] + c1.y*vh[j+1] + c1.z*vh[j+2] + c1.w*vh[j+3];
        float sv0 = s0 / (1.f + __expf(-s0));
        float sv1 = s1 / (1.f + __expf(-s1));
        __half2 gh = gatep[base + (size_t)j*E2];
        vgp[base + (size_t)j*E2] = __floats2half2_rn(sv0 * __low2float(gh), sv1 * __high2float(gh));
    }
}

// ---------------- launch ----------------
extern "C" void kernel_launch(void* const* d_in, const int* in_sizes, int n_in,
                              void* d_out, int out_size) {
    const float* x         = (const float*)d_in[0];
    const float* norm_w    = (const float*)d_in[1];
    const float* proj_w    = (const float*)d_in[2];
    const float* gate_w    = (const float*)d_in[3];
    const float* conv_w    = (const float*)d_in[4];
    const float* conv_b    = (const float*)d_in[5];
    const float* out_projw = (const float*)d_in[6];
    const float* write_w   = (const float*)d_in[7];
    const float* read_w    = (const float*)d_in[8];
    const float* decay     = (const float*)d_in[9];
    const float* log_alpha = (const float*)d_in[10];
    float* out = (float*)d_out;

    cudaFuncSetAttribute(k_mma, cudaFuncAttributeMaxDynamicSharedMemorySize, SMEM_BYTES);

    __half *p_yh, *p_vg, *p_outh, *p_reads, *p_wh;
    cudaGetSymbolAddress((void**)&p_yh,    g_yh);
    cudaGetSymbolAddress((void**)&p_vg,    g_vg);
    cudaGetSymbolAddress((void**)&p_outh,  g_out_h);
    cudaGetSymbolAddress((void**)&p_reads, g_reads);
    cudaGetSymbolAddress((void**)&p_wh,    g_wh);

    // 0) round weights to fp16
    k_wround<<<dim3((DI*DD + 255)/256, 5), 256>>>(proj_w, gate_w, out_projw, write_w, read_w);
    // 1) rmsnorm (fp16 out)
    k_rms<<<BT, 192>>>(x, norm_w);
    // 2) fused: [val | silu(gate)] = y @ [proj_w ; gate_w]^T  (fp16 out, N=3072)
    k_mma<<<dim3(2*DI/128, BT/128), THREADS, SMEM_BYTES>>>(p_yh, p_wh + W_PROJ, nullptr, DD, DD, DI, DD, M_PROJGATE, nullptr, nullptr, nullptr);
    // 3) vg = silu(conv(val)+b) * gate_silu  (fp16 out)
    k_conv<<<(unsigned)((size_t)BT/4*E2/256), 256>>>(conv_w, conv_b);
    // 4) out = vg @ out_proj_w^T  (fp16)
    k_mma<<<dim3(DD/128, BT/128), THREADS, SMEM_BYTES>>>(p_vg, p_wh + W_OUTP, nullptr, DI, DI, DD, DI, M_OUT, nullptr, nullptr, nullptr);
    // 5) v^T = write_w @ out^T -> g_vt (direct, coalesced)
    k_mma<<<dim3(TT/128, DD/128, BB), THREADS, SMEM_BYTES>>>(p_wh + W_WRITE, p_outh, nullptr, DD, DD, 0, DD, M_VT, nullptr, nullptr, nullptr);
    // 6) P = decay-masked (out @ shifted-out^T), banded lower tiles (factorized exp)
    k_mma<<<dim3(TILES_PER_B, BB), THREADS, SMEM_BYTES>>>(nullptr, nullptr, nullptr, 0, 0, 0, DD, M_SCORES, nullptr, decay, nullptr);
    // 7) reads = P @ v  (banded K)
    k_mma<<<dim3(DD/128, NT_T, BB), THREADS, SMEM_BYTES>>>(nullptr, nullptr, nullptr, 0, 0, 0, 0, M_ATTN, nullptr, nullptr, nullptr);
    // 8) final = x + out + exp(log_alpha) * (reads @ read_w^T)
    k_mma<<<dim3(DD/128, BT/128), THREADS, SMEM_BYTES>>>(p_reads, p_wh + W_READ, out, DD, DD, DD, DD, M_FINAL, x, nullptr, log_alpha);
}

// round 14
// speedup vs baseline: 1.0505x; 1.0251x over previous
#include <cuda_runtime.h>
#include <cuda_fp16.h>
#include <cstdint>

#define BB 8
#define TT 4096
#define DD 768
#define DI 1536
#define BT (BB*TT)            // 32768 rows
#define NT_T (TT/128)         // 32 row tiles per batch
#define NBAND 10              // score band in 128-tiles (gamma^1152 ~ 9e-6)
#define NTRI  45              // NBAND*(NBAND-1)/2
#define TILES_PER_B 275       // 45 + (32-9)*10
#define VT_TILES 192          // (DD/128)*(TT/128)

#define BM 128
#define BN 128
#define BKH 64                // K per stage in halves (128 bytes/row)
#define THREADS 128           // 4 warps, 64x64 warp tiles
#define TILE_BYTES 16384      // 128 rows x 128 B
#define STAGE_BYTES (2*TILE_BYTES)
#define SMEM_BYTES (2*STAGE_BYTES)   // 64 KB -> 3 CTAs/SM

// weight scratch layout (half elements); proj+gate contiguous for fused GEMM
#define W_PROJ  0
#define W_GATE  1179648
#define W_OUTP  2359296
#define W_WRITE 3538944
#define W_READ  4128768
#define W_TOTAL 4718592

// ---------------- scratch ----------------
__device__ __half g_yh[(size_t)BT*DD];       // rmsnorm output (fp16)
__device__ __half g_val[(size_t)BT*DI];      // pre-conv projection (fp16)
__device__ __half g_gate[(size_t)BT*DI];     // silu(gate projection) (fp16)
__device__ __half g_vg[(size_t)BT*DI];       // conv*gate output (fp16)
__device__ __half g_out_h[(size_t)BT*DD];    // conv-mix output (fp16: GEMM input + residual)
__device__ __half g_vt[(size_t)BB*DD*TT];    // write projection transposed [B,D,T] (fp16)
__device__ __half g_reads[(size_t)BT*DD];    // attention reads (fp16)
__device__ __half g_P[(size_t)BB*TT*TT];     // decay-weighted scores (fp16, banded tiles)
__device__ __half g_wh[W_TOTAL];             // fp16 weights

// ---------------- helpers ----------------
__device__ __forceinline__ uint32_t smem_u32(const void* p){
    uint32_t a;
    asm("{ .reg .u64 t; cvta.to.shared.u64 t, %1; cvt.u32.u64 %0, t; }" : "=r"(a) : "l"(p));
    return a;
}
__device__ __forceinline__ void cp16(uint32_t dst, const __half* src, int sz){
    asm volatile("cp.async.cg.shared.global [%0], [%1], 16, %2;" :: "r"(dst), "l"(src), "r"(sz) : "memory");
}
__device__ __forceinline__ void cpcommit(){ asm volatile("cp.async.commit_group;" ::: "memory"); }
__device__ __forceinline__ void cpwait0(){ asm volatile("cp.async.wait_group 0;" ::: "memory"); }
#define LDSM4(r0,r1,r2,r3,addr) \
    asm volatile("ldmatrix.sync.aligned.m8n8.x4.shared.b16 {%0,%1,%2,%3}, [%4];" \
      : "=r"(r0),"=r"(r1),"=r"(r2),"=r"(r3) : "r"(addr))
__device__ __forceinline__ void mma_fp16(float* c, const uint32_t* a, const uint32_t* b){
    asm volatile("mma.sync.aligned.m16n8k16.row.col.f32.f16.f16.f32 "
      "{%0,%1,%2,%3}, {%4,%5,%6,%7}, {%8,%9}, {%0,%1,%2,%3};"
      : "+f"(c[0]),"+f"(c[1]),"+f"(c[2]),"+f"(c[3])
      : "r"(a[0]),"r"(a[1]),"r"(a[2]),"r"(a[3]), "r"(b[0]),"r"(b[1]));
}

// modes
#define M_PROJGATE 0  // fused val/gate GEMM (half out, tile-routed, silu on gate half)
#define M_VT       1  // v^T = write_w @ out^T  (direct, coalesced)
#define M_SCORES   2
#define M_ATTN     3
#define M_FINAL    4
#define M_OUT      5  // fp16 store to g_out_h
#define M_VTSC     6  // fused VT + SCORES launch (blockIdx.x < VT_TILES -> VT)

__global__ void __launch_bounds__(THREADS, 3) k_mma(
    const __half* __restrict__ A, const __half* __restrict__ B, float* __restrict__ C,
    int lda, int ldb, int ldc, int K, int mode,
    const float* __restrict__ xres,
    const float* __restrict__ p_decay, const float* __restrict__ p_logalpha)
{
    extern __shared__ char smem[];
    const uint32_t sb = smem_u32(smem);
    const int t = threadIdx.x;
    const int lane = t & 31, wid = t >> 5;
    const int g = lane >> 2, tg = lane & 3;
    const int warp_m = wid & 1, warp_n = wid >> 1;   // 2 x 2 warps, WM=64, WN=64

    // ---- resolve tile ----
    const __half *Ab, *Bb;
    int bm, bn, Kloc = K, negB = 0;
    int emode = mode, batch = 0;
    if (mode == M_VTSC){
        batch = blockIdx.y;
        int l = blockIdx.x;
        if (l < VT_TILES){
            emode = M_VT;
            bm = (l >> 5) * 128;          // write_w row tile (DD/128 = 6)
            bn = (l & 31) * 128;          // t tile (TT/128 = 32)
            Ab = A + (size_t)bm*DD;                                  // write_w
            Bb = B + (size_t)batch*TT*DD + (size_t)bn*DD;            // out rows
            lda = DD; ldb = DD; Kloc = DD;
        } else {
            emode = M_SCORES;
            int l2 = l - VT_TILES;
            int i, j;
            if (l2 < NTRI){
                i = (int)((sqrtf(8.0f*(float)l2 + 1.0f) - 1.0f) * 0.5f);
                while ((i+1)*(i+2)/2 <= l2) i++;
                while (i*(i+1)/2 > l2) i--;
                j = l2 - i*(i+1)/2;
            } else {
                int q = (l2 - NTRI) / NBAND, rmd = (l2 - NTRI) % NBAND;
                i = (NBAND-1) + q;
                j = i - (NBAND-1) + rmd;
            }
            bm = i*128; bn = j*128;
            const __half* Ob = g_out_h + (size_t)batch*TT*DD;
            Ab = Ob + (size_t)bm*DD;
            Bb = Ob + (long long)(bn-1)*DD;   // shifted keys; row -1 when bn==0
            negB = (bn == 0);
            lda = DD; ldb = DD; Kloc = DD;
        }
    } else if (mode == M_ATTN){
        batch = blockIdx.z;
        int it = blockIdx.y;
        bm = it*128; bn = blockIdx.x*128;
        int j0 = it - (NBAND-1); if (j0 < 0) j0 = 0;
        const int k0start = j0*128;
        Ab = g_P + (size_t)batch*TT*TT + (size_t)bm*TT + k0start;
        Bb = g_vt + (size_t)batch*DD*TT + (size_t)bn*TT + k0start;
        lda = TT; ldb = TT; Kloc = (it - j0 + 1)*128;
    } else {
        bm = blockIdx.y*128; bn = blockIdx.x*128;
        Ab = A + (size_t)bm*lda; Bb = B + (size_t)bn*ldb;
    }

    // ---- staging bases: 128 threads x 8 chunks; row = (t>>3)+16*i, c = t&7 ----
    const int r0 = t >> 3;             // 0..15
    const int c0 = t & 7;
    const __half* aSrc0 = Ab + (size_t)r0*lda + c0*8;
    const __half* bSrcR = Bb + (size_t)r0*ldb + c0*8;       // real B base
    const int bP0 = (negB && r0 == 0) ? 0 : 16;             // chunk-0 predicate
    const __half* bSrc0 = bP0 ? bSrcR : Ab;                 // safe addr when zfill
    const uint32_t dOff0 = (uint32_t)(r0*128 + ((c0 ^ (r0 & 7)) << 4));
    uint32_t aAddr[2], bAddr[2];
    #pragma unroll
    for (int i = 0; i < 2; i++){
        aAddr[i] = sb + (uint32_t)i * STAGE_BYTES;
        bAddr[i] = aAddr[i] + TILE_BYTES;
    }

    // ---- ldmatrix per-lane row offsets (bytes) ----
    const int lane7 = lane & 7;
    uint32_t rowA[4], rowB[4];
    #pragma unroll
    for (int mt = 0; mt < 4; mt++)
        rowA[mt] = (uint32_t)((warp_m*64 + mt*16 + (lane & 15)) * 128);
    #pragma unroll
    for (int np = 0; np < 4; np++)
        rowB[np] = (uint32_t)((warp_n*64 + np*16 + ((lane >> 4) << 3) + lane7) * 128);
    const int a_chi = lane >> 4;          // 0/1
    const int b_chi = (lane >> 3) & 1;    // 0/1

    float acc[4][8][4] = {};
    const int NS = Kloc / BKH;

    // prologue: stage 0
    #pragma unroll
    for (int i = 0; i < 8; i++){
        cp16(aAddr[0] + dOff0 + 2048*i, aSrc0 + (size_t)(16*i)*lda, 16);
        cp16(bAddr[0] + dOff0 + 2048*i, (i ? bSrcR + (size_t)(16*i)*ldb : bSrc0), i ? 16 : bP0);
    }
    cpcommit();

    for (int s = 0; s < NS; s++){
        cpwait0();                 // stage s resident
        __syncthreads();           // visibility + all warps done with the other buffer

        if (s + 1 < NS){           // issue stage s+1 into the other buffer
            const int nb = (s+1) & 1, k0 = (s+1)*BKH;
            #pragma unroll
            for (int i = 0; i < 8; i++){
                cp16(aAddr[nb] + dOff0 + 2048*i, aSrc0 + (size_t)(16*i)*lda + k0, 16);
                cp16(bAddr[nb] + dOff0 + 2048*i, (i ? bSrcR + (size_t)(16*i)*ldb : bSrc0) + k0, i ? 16 : bP0);
            }
        }
        cpcommit();

        const int buf = s & 1;
        const uint32_t Ab0 = aAddr[buf], Bb0 = bAddr[buf];
        #pragma unroll
        for (int ks = 0; ks < 4; ks++){
            const uint32_t csA = (uint32_t)(((2*ks + a_chi) ^ lane7) << 4);
            const uint32_t csB = (uint32_t)(((2*ks + b_chi) ^ lane7) << 4);
            uint32_t af[4][4], bf[8][2];
            #pragma unroll
            for (int mt = 0; mt < 4; mt++)
                LDSM4(af[mt][0], af[mt][1], af[mt][2], af[mt][3], Ab0 + rowA[mt] + csA);
            #pragma unroll
            for (int np = 0; np < 4; np++)
                LDSM4(bf[np*2][0], bf[np*2][1], bf[np*2+1][0], bf[np*2+1][1], Bb0 + rowB[np] + csB);
            #pragma unroll
            for (int mt = 0; mt < 4; mt++)
                #pragma unroll
                for (int nt = 0; nt < 8; nt++)
                    mma_fp16(acc[mt][nt], af[mt], bf[nt]);
        }
    }

    // ---------------- epilogues ----------------
    if (emode == M_SCORES){
        const float gammaLg = logf(1.0f / (1.0f + expf(-p_decay[0])));
        float rowE[8], colE[16];
        #pragma unroll
        for (int mt = 0; mt < 4; mt++)
            #pragma unroll
            for (int half = 0; half < 2; half++)
                rowE[mt*2+half] = __expf((float)(bm + warp_m*64 + mt*16 + g + half*8) * gammaLg);
        #pragma unroll
        for (int nt = 0; nt < 8; nt++)
            #pragma unroll
            for (int k = 0; k < 2; k++)
                colE[nt*2+k] = __expf(-(float)(bn + warp_n*64 + nt*8 + tg*2 + k + 1) * gammaLg);
        #pragma unroll
        for (int mt = 0; mt < 4; mt++){
            #pragma unroll
            for (int half = 0; half < 2; half++){
                const int r = warp_m*64 + mt*16 + g + half*8;
                const int trow = bm + r;
                const float er = rowE[mt*2+half];
                #pragma unroll
                for (int nt = 0; nt < 8; nt++){
                    const int c = warp_n*64 + nt*8 + tg*2;
                    const int d0 = trow - (bn + c) - 1;
                    float o0 = (d0 >= 0) ? acc[mt][nt][half*2]   * er * colE[nt*2]   : 0.f;
                    float o1 = (d0 >= 1) ? acc[mt][nt][half*2+1] * er * colE[nt*2+1] : 0.f;
                    __half* Pb = g_P + (size_t)batch*TT*TT + (size_t)trow*TT + bn + c;
                    *(__half2*)Pb = __floats2half2_rn(o0, o1);
                }
            }
        }
        return;
    }

    float alpha = 0.f;
    if (mode == M_FINAL) alpha = expf(p_logalpha[0]);
    __half* pgBase = nullptr; int pgCol = 0; bool isGate = false;
    if (mode == M_PROJGATE){
        isGate = (bn >= DI);
        pgBase = isGate ? g_gate : g_val;
        pgCol = isGate ? bn - DI : bn;
    }
    __half* vtBase = (emode == M_VT) ? g_vt + (size_t)batch*DD*TT : nullptr;
    __half* rdBase = (mode == M_ATTN) ? g_reads + (size_t)batch*TT*DD : nullptr;

    #pragma unroll
    for (int mt = 0; mt < 4; mt++){
        #pragma unroll
        for (int half = 0; half < 2; half++){
            const int r = warp_m*64 + mt*16 + g + half*8;
            #pragma unroll
            for (int nt = 0; nt < 8; nt++){
                const int c = warp_n*64 + nt*8 + tg*2;
                float v0 = acc[mt][nt][half*2];
                float v1 = acc[mt][nt][half*2 + 1];
                if (mode == M_FINAL){
                    size_t idx = (size_t)(bm + r)*DD + bn + c;
                    float2 xv = *(const float2*)(xres + idx);
                    __half2 oh = *(const __half2*)(g_out_h + idx);
                    *(float2*)(C + idx) = make_float2(xv.x + __low2float(oh) + alpha*v0,
                                                      xv.y + __high2float(oh) + alpha*v1);
                } else if (mode == M_OUT){
                    size_t idx = (size_t)(bm + r)*DD + bn + c;
                    *(__half2*)(g_out_h + idx) = __floats2half2_rn(v0, v1);
                } else if (emode == M_VT){
                    *(__half2*)(vtBase + (size_t)(bm + r)*TT + bn + c) = __floats2half2_rn(v0, v1);
                } else if (mode == M_ATTN){
                    *(__half2*)(rdBase + (size_t)(bm + r)*DD + bn + c) = __floats2half2_rn(v0, v1);
                } else { // M_PROJGATE
                    if (isGate){
                        v0 = v0 / (1.f + __expf(-v0));
                        v1 = v1 / (1.f + __expf(-v1));
                    }
                    *(__half2*)(pgBase + (size_t)(bm + r)*DI + pgCol + c) = __floats2half2_rn(v0, v1);
                }
            }
        }
    }
}

// ---------------- weight rounding (5 matrices -> g_wh) ----------------
__global__ void k_wround(const float* __restrict__ s0, const float* __restrict__ s1,
                         const float* __restrict__ s2, const float* __restrict__ s3,
                         const float* __restrict__ s4)
{
    int m = blockIdx.y;
    int idx = blockIdx.x * 256 + threadIdx.x;
    const float* src; int off, n;
    switch (m){
        case 0: src = s0; off = W_PROJ;  n = DI*DD; break;
        case 1: src = s1; off = W_GATE;  n = DI*DD; break;
        case 2: src = s2; off = W_OUTP;  n = DD*DI; break;
        case 3: src = s3; off = W_WRITE; n = DD*DD; break;
        default: src = s4; off = W_READ; n = DD*DD; break;
    }
    if (idx < n) g_wh[off + idx] = __float2half_rn(src[idx]);
}

// ---------------- rmsnorm: 192 threads/row, float4 + warp shuffle ----------------
__global__ void __launch_bounds__(192) k_rms(const float* __restrict__ x, const float* __restrict__ w) {
    const int row = blockIdx.x;
    const int tid = threadIdx.x;           // 0..191
    const int lane = tid & 31, wd = tid >> 5;
    const float4 v = ((const float4*)(x + (size_t)row * DD))[tid];
    float s = v.x*v.x + v.y*v.y + v.z*v.z + v.w*v.w;
    #pragma unroll
    for (int off = 16; off > 0; off >>= 1)
        s += __shfl_xor_sync(0xffffffffu, s, off);
    __shared__ float ws[6];
    if (lane == 0) ws[wd] = s;
    __syncthreads();
    float tot = ws[0] + ws[1] + ws[2] + ws[3] + ws[4] + ws[5];
    float r = rsqrtf(tot * (1.0f/DD) + 1e-5f);
    const float4 wv = ((const float4*)w)[tid];
    __half2* yr = (__half2*)(g_yh + (size_t)row * DD);
    yr[tid*2]   = __floats2half2_rn(v.x * r * wv.x, v.y * r * wv.y);
    yr[tid*2+1] = __floats2half2_rn(v.z * r * wv.z, v.w * r * wv.w);
}

// ---- depthwise causal conv + (pre-silu'd) gate (half2 channels, 4 t/thread) ----
#define E2 (DI/2)
__global__ void k_conv(const float* __restrict__ cw, const float* __restrict__ cb) {
    size_t idx = (size_t)blockIdx.x * 256 + threadIdx.x;   // (BT/4)*E2 threads
    int e2 = (int)(idx % E2);
    size_t q = idx / E2;
    int tq = (int)(q % (TT/4));
    int b  = (int)(q / (TT/4));
    int t0 = tq * 4;
    const int e0 = e2 * 2;
    size_t base = (((size_t)b*TT + t0)*DI >> 1) + e2;       // half2 index
    const float4 c0 = ((const float4*)cw)[e0];
    const float4 c1 = ((const float4*)cw)[e0+1];
    const float2 bias = ((const float2*)cb)[e2];
    const __half2* valp = (const __half2*)g_val;
    const __half2* gatep = (const __half2*)g_gate;          // already silu'd
    __half2* vgp = (__half2*)g_vg;
    float vl[7], vh[7];
    #pragma unroll
    for (int i = 0; i < 7; i++){
        int tt = t0 - 3 + i;
        if (tt >= 0){
            __half2 hv = valp[base + (size_t)(i-3)*E2];
            vl[i] = __low2float(hv); vh[i] = __high2float(hv);
        } else { vl[i] = 0.f; vh[i] = 0.f; }
    }
    #pragma unroll
    for (int j = 0; j < 4; j++){
        float s0 = bias.x + c0.x*vl[j] + c0.y*vl[j+1] + c0.z*vl[j+2] + c0.w*vl[j+3];
        float s1 = bias.y + c1.x*vh[j] + c1.y*vh[j+1] + c1.z*vh[j+2] + c1.w*vh[j+3];
        float sv0 = s0 / (1.f + __expf(-s0));
        float sv1 = s1 / (1.f + __expf(-s1));
        __half2 gh = gatep[base + (size_t)j*E2];
        vgp[base + (size_t)j*E2] = __floats2half2_rn(sv0 * __low2float(gh), sv1 * __high2float(gh));
    }
}

// ---------------- launch ----------------
extern "C" void kernel_launch(void* const* d_in, const int* in_sizes, int n_in,
                              void* d_out, int out_size) {
    const float* x         = (const float*)d_in[0];
    const float* norm_w    = (const float*)d_in[1];
    const float* proj_w    = (const float*)d_in[2];
    const float* gate_w    = (const float*)d_in[3];
    const float* conv_w    = (const float*)d_in[4];
    const float* conv_b    = (const float*)d_in[5];
    const float* out_projw = (const float*)d_in[6];
    const float* write_w   = (const float*)d_in[7];
    const float* read_w    = (const float*)d_in[8];
    const float* decay     = (const float*)d_in[9];
    const float* log_alpha = (const float*)d_in[10];
    float* out = (float*)d_out;

    cudaFuncSetAttribute(k_mma, cudaFuncAttributeMaxDynamicSharedMemorySize, SMEM_BYTES);

    __half *p_yh, *p_vg, *p_outh, *p_reads, *p_wh;
    cudaGetSymbolAddress((void**)&p_yh,    g_yh);
    cudaGetSymbolAddress((void**)&p_vg,    g_vg);
    cudaGetSymbolAddress((void**)&p_outh,  g_out_h);
    cudaGetSymbolAddress((void**)&p_reads, g_reads);
    cudaGetSymbolAddress((void**)&p_wh,    g_wh);

    // 0) round weights to fp16
    k_wround<<<dim3((DI*DD + 255)/256, 5), 256>>>(proj_w, gate_w, out_projw, write_w, read_w);
    // 1) rmsnorm (fp16 out)
    k_rms<<<BT, 192>>>(x, norm_w);
    // 2) fused: [val | silu(gate)] = y @ [proj_w ; gate_w]^T  (fp16 out, N=3072)
    k_mma<<<dim3(2*DI/128, BT/128), THREADS, SMEM_BYTES>>>(p_yh, p_wh + W_PROJ, nullptr, DD, DD, DI, DD, M_PROJGATE, nullptr, nullptr, nullptr);
    // 3) vg = silu(conv(val)+b) * gate_silu  (fp16 out)
    k_conv<<<(unsigned)((size_t)BT/4*E2/256), 256>>>(conv_w, conv_b);
    // 4) out = vg @ out_proj_w^T  (fp16)
    k_mma<<<dim3(DD/128, BT/128), THREADS, SMEM_BYTES>>>(p_vg, p_wh + W_OUTP, nullptr, DI, DI, DD, DI, M_OUT, nullptr, nullptr, nullptr);
    // 5+6) fused: v^T = write_w @ out^T  AND  P = decay-masked scores (banded)
    k_mma<<<dim3(VT_TILES + TILES_PER_B, BB), THREADS, SMEM_BYTES>>>(p_wh + W_WRITE, p_outh, nullptr, DD, DD, 0, DD, M_VTSC, nullptr, decay, nullptr);
    // 7) reads = P @ v  (banded K)
    k_mma<<<dim3(DD/128, NT_T, BB), THREADS, SMEM_BYTES>>>(nullptr, nullptr, nullptr, 0, 0, 0, 0, M_ATTN, nullptr, nullptr, nullptr);
    // 8) final = x + out + exp(log_alpha) * (reads @ read_w^T)
    k_mma<<<dim3(DD/128, BT/128), THREADS, SMEM_BYTES>>>(p_reads, p_wh + W_READ, out, DD, DD, DD, DD, M_FINAL, x, nullptr, log_alpha);
}